// round 7
// baseline (speedup 1.0000x reference)
#include <cuda_runtime.h>
#include <cuda_bf16.h>
#include <cstdint>

#define N_NODES   100000
#define N_EDGES   1600000
#define N_WEIGHTS 256
#define D         16
#define SC_ITER   4
#define SC_CHUNK  (256 * SC_ITER)   // 1024 edges per scatter block
#define MM_GRID_Y 10                // blocks per bin in edge_mm
#define BIN_CAP   8192              // fixed slots per bin (≥ max bin count ~6600)

// ---------------- scratch ----------------
__device__ int  g_bin_fill[N_WEIGHTS];
__device__ int2 g_suv[N_WEIGHTS * BIN_CAP];

// ---------------- helpers ----------------
__device__ __forceinline__ unsigned long long pack2(float lo, float hi) {
    unsigned long long r;
    asm("mov.b64 %0, {%1, %2};" : "=l"(r) : "f"(lo), "f"(hi));
    return r;
}
__device__ __forceinline__ void fma2(unsigned long long& d,
                                     unsigned long long a, unsigned long long b) {
    asm("fma.rn.f32x2 %0, %1, %2, %0;" : "+l"(d) : "l"(a), "l"(b));
}
__device__ __forceinline__ void unpack2(unsigned long long v, float& lo, float& hi) {
    asm("mov.b64 {%0, %1}, %2;" : "=f"(lo), "=f"(hi) : "l"(v));
}
__device__ __forceinline__ void red_add_v4(float* p, float a, float b, float c, float d) {
    asm volatile("red.global.add.v4.f32 [%0], {%1, %2, %3, %4};"
                 :: "l"(p), "f"(a), "f"(b), "f"(c), "f"(d) : "memory");
}

// ---------------- kernels ----------------

__global__ void fill_init_k() {
    int t = threadIdx.x;
    g_bin_fill[t] = t * BIN_CAP;
}

// One-pass counting-sort scatter into bump-allocated bin regions.
__global__ void __launch_bounds__(256)
scatter_k(const int* __restrict__ u, const int* __restrict__ v,
          const int* __restrict__ widx, int E) {
    __shared__ int  cnt[N_WEIGHTS];
    __shared__ int  lstart[N_WEIGHTS];
    __shared__ int  gbase[N_WEIGHTS];
    __shared__ int  wsum[8];
    __shared__ int2 sval[SC_CHUNK];
    __shared__ unsigned char sbin[SC_CHUNK];

    const int tid  = threadIdx.x;
    const int lane = tid & 31;
    const int wrp  = tid >> 5;
    const int blk0 = blockIdx.x * SC_CHUNK;
    if (blk0 >= E) return;
    const int n = min(SC_CHUNK, E - blk0);

    cnt[tid] = 0;
    __syncthreads();

    int eu[SC_ITER], ev[SC_ITER], ew[SC_ITER], er[SC_ITER];
#pragma unroll
    for (int i = 0; i < SC_ITER; i++) {
        int e = blk0 + tid + i * 256;
        if (e < E) {
            ew[i] = widx[e];
            eu[i] = u[e];
            ev[i] = v[e];
            er[i] = atomicAdd(&cnt[ew[i]], 1);
        }
    }
    __syncthreads();

    // shuffle-based exclusive block scan of cnt[256]
    {
        const int c = cnt[tid];
        int s = c;
#pragma unroll
        for (int off = 1; off < 32; off <<= 1) {
            int t = __shfl_up_sync(0xffffffffu, s, off);
            if (lane >= off) s += t;
        }
        if (lane == 31) wsum[wrp] = s;
        __syncthreads();
        if (wrp == 0 && lane < 8) {
            int t = wsum[lane];
#pragma unroll
            for (int off = 1; off < 8; off <<= 1) {
                int q = __shfl_up_sync(0xffu, t, off);
                if (lane >= off) t += q;
            }
            wsum[lane] = t;
        }
        __syncthreads();
        int incl = s + (wrp ? wsum[wrp - 1] : 0);
        lstart[tid] = incl - c;
        gbase[tid]  = c ? atomicAdd(&g_bin_fill[tid], c) : 0;
    }
    __syncthreads();

#pragma unroll
    for (int i = 0; i < SC_ITER; i++) {
        int e = blk0 + tid + i * 256;
        if (e < E) {
            int slot = lstart[ew[i]] + er[i];
            sval[slot] = make_int2(eu[i], ev[i]);
            sbin[slot] = (unsigned char)ew[i];
        }
    }
    __syncthreads();

    for (int s = tid; s < n; s += 256) {
        int b = sbin[s];
        g_suv[gbase[b] + (s - lstart[b])] = sval[s];
    }
}

// Warp-autonomous edge kernel with uv software pipelining.
__global__ void __launch_bounds__(256)
edge_mm_k(const float* __restrict__ x, const float* __restrict__ W,
          float* __restrict__ out) {
    const int w  = blockIdx.x;
    const int bs = w * BIN_CAP;
    const int be = g_bin_fill[w];      // post-scatter: bs + bin_count

    const int tid   = threadIdx.x;
    const int lane  = tid & 31;
    const int wid   = tid >> 5;
    const int qrt   = lane & 3;
    const int el    = lane >> 2;
    const int obase = qrt * 4;

    const float* Wb = W + (size_t)w * (D * D);
    unsigned long long wp0[D], wp1[D];
#pragma unroll
    for (int k = 0; k < D; k++) {
        wp0[k] = pack2(Wb[(obase + 0) * D + k], Wb[(obase + 1) * D + k]);
        wp1[k] = pack2(Wb[(obase + 2) * D + k], Wb[(obase + 3) * D + k]);
    }

    __shared__ float4 xs[8][16 * 5];

    const float4* x4 = (const float4*)x;
    const int gw   = blockIdx.y * 8 + wid;
    const int step = gridDim.y * 8 * 16;

    int e0 = bs + gw * 16;
    if (e0 >= be) return;

    int2 uvA = (e0 + el     < be) ? g_suv[e0 + el]     : make_int2(0, 0);
    int2 uvB = (e0 + 8 + el < be) ? g_suv[e0 + 8 + el] : make_int2(0, 0);

    for (; e0 < be; e0 += step) {
        const bool pA = (e0 + el     < be);
        const bool pB = (e0 + 8 + el < be);

        float4 xqA = x4[(size_t)uvA.x * 4 + qrt];
        float4 xqB = x4[(size_t)uvB.x * 4 + qrt];

        const int e1 = e0 + step;
        int2 nA = (e1 + el     < be) ? g_suv[e1 + el]     : make_int2(0, 0);
        int2 nB = (e1 + 8 + el < be) ? g_suv[e1 + 8 + el] : make_int2(0, 0);

        xs[wid][el * 5 + qrt]       = xqA;
        xs[wid][(8 + el) * 5 + qrt] = xqB;
        __syncwarp();

        unsigned long long a0A = 0ull, a1A = 0ull, a0B = 0ull, a1B = 0ull;
#pragma unroll
        for (int q = 0; q < 4; q++) {
            float4 xA = xs[wid][el * 5 + q];
            float4 xB = xs[wid][(8 + el) * 5 + q];
            unsigned long long bA0 = pack2(xA.x, xA.x), bB0 = pack2(xB.x, xB.x);
            unsigned long long bA1 = pack2(xA.y, xA.y), bB1 = pack2(xB.y, xB.y);
            unsigned long long bA2 = pack2(xA.z, xA.z), bB2 = pack2(xB.z, xB.z);
            unsigned long long bA3 = pack2(xA.w, xA.w), bB3 = pack2(xB.w, xB.w);
            fma2(a0A, wp0[q * 4 + 0], bA0);  fma2(a1A, wp1[q * 4 + 0], bA0);
            fma2(a0B, wp0[q * 4 + 0], bB0);  fma2(a1B, wp1[q * 4 + 0], bB0);
            fma2(a0A, wp0[q * 4 + 1], bA1);  fma2(a1A, wp1[q * 4 + 1], bA1);
            fma2(a0B, wp0[q * 4 + 1], bB1);  fma2(a1B, wp1[q * 4 + 1], bB1);
            fma2(a0A, wp0[q * 4 + 2], bA2);  fma2(a1A, wp1[q * 4 + 2], bA2);
            fma2(a0B, wp0[q * 4 + 2], bB2);  fma2(a1B, wp1[q * 4 + 2], bB2);
            fma2(a0A, wp0[q * 4 + 3], bA3);  fma2(a1A, wp1[q * 4 + 3], bA3);
            fma2(a0B, wp0[q * 4 + 3], bB3);  fma2(a1B, wp1[q * 4 + 3], bB3);
        }

        if (pA) {
            float r0, r1, r2, r3;
            unpack2(a0A, r0, r1);
            unpack2(a1A, r2, r3);
            red_add_v4(out + (size_t)uvA.y * D + obase, r0, r1, r2, r3);
        }
        if (pB) {
            float r0, r1, r2, r3;
            unpack2(a0B, r0, r1);
            unpack2(a1B, r2, r3);
            red_add_v4(out + (size_t)uvB.y * D + obase, r0, r1, r2, r3);
        }
        __syncwarp();

        uvA = nA;
        uvB = nB;
    }
}

__global__ void __launch_bounds__(256)
relu_k(float* __restrict__ out, int n4) {
    int i = blockIdx.x * blockDim.x + threadIdx.x;
    if (i < n4) {
        float4* o4 = (float4*)out;
        float4 v = o4[i];
        v.x = fmaxf(v.x, 0.f);
        v.y = fmaxf(v.y, 0.f);
        v.z = fmaxf(v.z, 0.f);
        v.w = fmaxf(v.w, 0.f);
        o4[i] = v;
    }
}

// ---------------- launcher ----------------
extern "C" void kernel_launch(void* const* d_in, const int* in_sizes, int n_in,
                              void* d_out, int out_size) {
    const float* x    = (const float*)d_in[0];
    const float* W    = (const float*)d_in[1];
    const int*   u    = (const int*)d_in[2];
    const int*   v    = (const int*)d_in[3];
    const int*   widx = (const int*)d_in[4];
    float* out = (float*)d_out;

    const int E = in_sizes[2];

    cudaMemsetAsync(d_out, 0, (size_t)out_size * sizeof(float), 0);

    fill_init_k<<<1, 256>>>();
    scatter_k<<<(E + SC_CHUNK - 1) / SC_CHUNK, 256>>>(u, v, widx, E);
    edge_mm_k<<<dim3(N_WEIGHTS, MM_GRID_Y), 256>>>(x, W, out);
    int n4 = out_size / 4;
    relu_k<<<(n4 + 255) / 256, 256>>>(out, n4);
}

// round 8
// speedup vs baseline: 1.0817x; 1.0817x over previous
#include <cuda_runtime.h>
#include <cuda_bf16.h>
#include <cstdint>

#define N_NODES   100000
#define N_EDGES   1600000
#define N_WEIGHTS 256
#define D         16
#define SC_ITER   8
#define SC_CHUNK  (256 * SC_ITER)   // 2048 edges per scatter block
#define MM_GRID_Y 10                // blocks per bin in edge_mm
#define BIN_CAP   8192              // fixed slots per bin (≥ max bin count ~6600)

// ---------------- scratch ----------------
__device__ int  g_bin_fill[N_WEIGHTS];
__device__ int2 g_suv[N_WEIGHTS * BIN_CAP];

// ---------------- helpers ----------------
__device__ __forceinline__ unsigned long long pack2(float lo, float hi) {
    unsigned long long r;
    asm("mov.b64 %0, {%1, %2};" : "=l"(r) : "f"(lo), "f"(hi));
    return r;
}
__device__ __forceinline__ void fma2(unsigned long long& d,
                                     unsigned long long a, unsigned long long b) {
    asm("fma.rn.f32x2 %0, %1, %2, %0;" : "+l"(d) : "l"(a), "l"(b));
}
__device__ __forceinline__ void unpack2(unsigned long long v, float& lo, float& hi) {
    asm("mov.b64 {%0, %1}, %2;" : "=f"(lo), "=f"(hi) : "l"(v));
}
__device__ __forceinline__ void red_add_v4(float* p, float a, float b, float c, float d) {
    asm volatile("red.global.add.v4.f32 [%0], {%1, %2, %3, %4};"
                 :: "l"(p), "f"(a), "f"(b), "f"(c), "f"(d) : "memory");
}

// ---------------- kernels ----------------

__global__ void fill_init_k() {
    int t = threadIdx.x;
    g_bin_fill[t] = t * BIN_CAP;
}

// One-pass counting-sort scatter into bump-allocated bin regions.
// Each thread owns 8 CONSECUTIVE edges -> int4-vectorized loads.
__global__ void __launch_bounds__(256)
scatter_k(const int* __restrict__ u, const int* __restrict__ v,
          const int* __restrict__ widx, int E) {
    __shared__ int  cnt[N_WEIGHTS];
    __shared__ int  lstart[N_WEIGHTS];
    __shared__ int  gbase[N_WEIGHTS];
    __shared__ int  wsum[8];
    __shared__ int2 sval[SC_CHUNK];
    __shared__ unsigned char sbin[SC_CHUNK];

    const int tid  = threadIdx.x;
    const int lane = tid & 31;
    const int wrp  = tid >> 5;
    const int blk0 = blockIdx.x * SC_CHUNK;
    if (blk0 >= E) return;
    const int n = min(SC_CHUNK, E - blk0);

    cnt[tid] = 0;
    __syncthreads();

    // 8 consecutive edges per thread; E % 8 == 0 so each thread is all-in or all-out
    const int e0 = blk0 + tid * SC_ITER;
    const bool act = (e0 < E);

    int eu[SC_ITER], ev[SC_ITER], ew[SC_ITER], er[SC_ITER];
    if (act) {
        const int4* u4 = (const int4*)(u + e0);
        const int4* v4 = (const int4*)(v + e0);
        const int4* w4 = (const int4*)(widx + e0);
        int4 ua = u4[0], ub = u4[1];
        int4 va = v4[0], vb = v4[1];
        int4 wa = w4[0], wb = w4[1];
        eu[0]=ua.x; eu[1]=ua.y; eu[2]=ua.z; eu[3]=ua.w;
        eu[4]=ub.x; eu[5]=ub.y; eu[6]=ub.z; eu[7]=ub.w;
        ev[0]=va.x; ev[1]=va.y; ev[2]=va.z; ev[3]=va.w;
        ev[4]=vb.x; ev[5]=vb.y; ev[6]=vb.z; ev[7]=vb.w;
        ew[0]=wa.x; ew[1]=wa.y; ew[2]=wa.z; ew[3]=wa.w;
        ew[4]=wb.x; ew[5]=wb.y; ew[6]=wb.z; ew[7]=wb.w;
#pragma unroll
        for (int i = 0; i < SC_ITER; i++)
            er[i] = atomicAdd(&cnt[ew[i]], 1);
    }
    __syncthreads();

    // shuffle-based exclusive block scan of cnt[256]
    {
        const int c = cnt[tid];
        int s = c;
#pragma unroll
        for (int off = 1; off < 32; off <<= 1) {
            int t = __shfl_up_sync(0xffffffffu, s, off);
            if (lane >= off) s += t;
        }
        if (lane == 31) wsum[wrp] = s;
        __syncthreads();
        if (wrp == 0 && lane < 8) {
            int t = wsum[lane];
#pragma unroll
            for (int off = 1; off < 8; off <<= 1) {
                int q = __shfl_up_sync(0xffu, t, off);
                if (lane >= off) t += q;
            }
            wsum[lane] = t;
        }
        __syncthreads();
        int incl = s + (wrp ? wsum[wrp - 1] : 0);
        lstart[tid] = incl - c;
        gbase[tid]  = c ? atomicAdd(&g_bin_fill[tid], c) : 0;
    }
    __syncthreads();

    if (act) {
#pragma unroll
        for (int i = 0; i < SC_ITER; i++) {
            int slot = lstart[ew[i]] + er[i];
            sval[slot] = make_int2(eu[i], ev[i]);
            sbin[slot] = (unsigned char)ew[i];
        }
    }
    __syncthreads();

    for (int s = tid; s < n; s += 256) {
        int b = sbin[s];
        g_suv[gbase[b] + (s - lstart[b])] = sval[s];
    }
}

// Warp-autonomous edge kernel with uv software pipelining.
__global__ void __launch_bounds__(256)
edge_mm_k(const float* __restrict__ x, const float* __restrict__ W,
          float* __restrict__ out) {
    const int w  = blockIdx.x;
    const int bs = w * BIN_CAP;
    const int be = g_bin_fill[w];      // post-scatter: bs + bin_count

    const int tid   = threadIdx.x;
    const int lane  = tid & 31;
    const int wid   = tid >> 5;
    const int qrt   = lane & 3;
    const int el    = lane >> 2;
    const int obase = qrt * 4;

    const float* Wb = W + (size_t)w * (D * D);
    unsigned long long wp0[D], wp1[D];
#pragma unroll
    for (int k = 0; k < D; k++) {
        wp0[k] = pack2(Wb[(obase + 0) * D + k], Wb[(obase + 1) * D + k]);
        wp1[k] = pack2(Wb[(obase + 2) * D + k], Wb[(obase + 3) * D + k]);
    }

    __shared__ float4 xs[8][16 * 5];

    const float4* x4 = (const float4*)x;
    const int gw   = blockIdx.y * 8 + wid;
    const int step = gridDim.y * 8 * 16;

    int e0 = bs + gw * 16;
    if (e0 >= be) return;

    int2 uvA = (e0 + el     < be) ? g_suv[e0 + el]     : make_int2(0, 0);
    int2 uvB = (e0 + 8 + el < be) ? g_suv[e0 + 8 + el] : make_int2(0, 0);

    for (; e0 < be; e0 += step) {
        const bool pA = (e0 + el     < be);
        const bool pB = (e0 + 8 + el < be);

        float4 xqA = x4[(size_t)uvA.x * 4 + qrt];
        float4 xqB = x4[(size_t)uvB.x * 4 + qrt];

        const int e1 = e0 + step;
        int2 nA = (e1 + el     < be) ? g_suv[e1 + el]     : make_int2(0, 0);
        int2 nB = (e1 + 8 + el < be) ? g_suv[e1 + 8 + el] : make_int2(0, 0);

        xs[wid][el * 5 + qrt]       = xqA;
        xs[wid][(8 + el) * 5 + qrt] = xqB;
        __syncwarp();

        unsigned long long a0A = 0ull, a1A = 0ull, a0B = 0ull, a1B = 0ull;
#pragma unroll
        for (int q = 0; q < 4; q++) {
            float4 xA = xs[wid][el * 5 + q];
            float4 xB = xs[wid][(8 + el) * 5 + q];
            unsigned long long bA0 = pack2(xA.x, xA.x), bB0 = pack2(xB.x, xB.x);
            unsigned long long bA1 = pack2(xA.y, xA.y), bB1 = pack2(xB.y, xB.y);
            unsigned long long bA2 = pack2(xA.z, xA.z), bB2 = pack2(xB.z, xB.z);
            unsigned long long bA3 = pack2(xA.w, xA.w), bB3 = pack2(xB.w, xB.w);
            fma2(a0A, wp0[q * 4 + 0], bA0);  fma2(a1A, wp1[q * 4 + 0], bA0);
            fma2(a0B, wp0[q * 4 + 0], bB0);  fma2(a1B, wp1[q * 4 + 0], bB0);
            fma2(a0A, wp0[q * 4 + 1], bA1);  fma2(a1A, wp1[q * 4 + 1], bA1);
            fma2(a0B, wp0[q * 4 + 1], bB1);  fma2(a1B, wp1[q * 4 + 1], bB1);
            fma2(a0A, wp0[q * 4 + 2], bA2);  fma2(a1A, wp1[q * 4 + 2], bA2);
            fma2(a0B, wp0[q * 4 + 2], bB2);  fma2(a1B, wp1[q * 4 + 2], bB2);
            fma2(a0A, wp0[q * 4 + 3], bA3);  fma2(a1A, wp1[q * 4 + 3], bA3);
            fma2(a0B, wp0[q * 4 + 3], bB3);  fma2(a1B, wp1[q * 4 + 3], bB3);
        }

        if (pA) {
            float r0, r1, r2, r3;
            unpack2(a0A, r0, r1);
            unpack2(a1A, r2, r3);
            red_add_v4(out + (size_t)uvA.y * D + obase, r0, r1, r2, r3);
        }
        if (pB) {
            float r0, r1, r2, r3;
            unpack2(a0B, r0, r1);
            unpack2(a1B, r2, r3);
            red_add_v4(out + (size_t)uvB.y * D + obase, r0, r1, r2, r3);
        }
        __syncwarp();

        uvA = nA;
        uvB = nB;
    }
}

__global__ void __launch_bounds__(256)
relu_k(float* __restrict__ out, int n4) {
    int i = blockIdx.x * blockDim.x + threadIdx.x;
    if (i < n4) {
        float4* o4 = (float4*)out;
        float4 v = o4[i];
        v.x = fmaxf(v.x, 0.f);
        v.y = fmaxf(v.y, 0.f);
        v.z = fmaxf(v.z, 0.f);
        v.w = fmaxf(v.w, 0.f);
        o4[i] = v;
    }
}

// ---------------- launcher ----------------
extern "C" void kernel_launch(void* const* d_in, const int* in_sizes, int n_in,
                              void* d_out, int out_size) {
    const float* x    = (const float*)d_in[0];
    const float* W    = (const float*)d_in[1];
    const int*   u    = (const int*)d_in[2];
    const int*   v    = (const int*)d_in[3];
    const int*   widx = (const int*)d_in[4];
    float* out = (float*)d_out;

    const int E = in_sizes[2];

    cudaMemsetAsync(d_out, 0, (size_t)out_size * sizeof(float), 0);

    fill_init_k<<<1, 256>>>();
    scatter_k<<<(E + SC_CHUNK - 1) / SC_CHUNK, 256>>>(u, v, widx, E);
    edge_mm_k<<<dim3(N_WEIGHTS, MM_GRID_Y), 256>>>(x, W, out);
    int n4 = out_size / 4;
    relu_k<<<(n4 + 255) / 256, 256>>>(out, n4);
}

// round 9
// speedup vs baseline: 1.0851x; 1.0031x over previous
#include <cuda_runtime.h>
#include <cuda_bf16.h>
#include <cstdint>

#define N_NODES   100000
#define N_EDGES   1600000
#define N_WEIGHTS 256
#define D         16
#define SC_ITER   8
#define SC_CHUNK  (256 * SC_ITER)   // 2048 edges per scatter block
#define MM_GRID_Y 10                // blocks per bin in edge_mm
#define BIN_CAP   8192              // fixed slots per bin (≥ max bin count ~6600)

// ---------------- scratch ----------------
__device__ int  g_bin_fill[N_WEIGHTS];
__device__ int2 g_suv[N_WEIGHTS * BIN_CAP];

// ---------------- helpers ----------------
__device__ __forceinline__ unsigned long long pack2(float lo, float hi) {
    unsigned long long r;
    asm("mov.b64 %0, {%1, %2};" : "=l"(r) : "f"(lo), "f"(hi));
    return r;
}
__device__ __forceinline__ void fma2(unsigned long long& d,
                                     unsigned long long a, unsigned long long b) {
    asm("fma.rn.f32x2 %0, %1, %2, %0;" : "+l"(d) : "l"(a), "l"(b));
}
__device__ __forceinline__ void unpack2(unsigned long long v, float& lo, float& hi) {
    asm("mov.b64 {%0, %1}, %2;" : "=f"(lo), "=f"(hi) : "l"(v));
}
__device__ __forceinline__ void red_add_v4(float* p, float a, float b, float c, float d) {
    asm volatile("red.global.add.v4.f32 [%0], {%1, %2, %3, %4};"
                 :: "l"(p), "f"(a), "f"(b), "f"(c), "f"(d) : "memory");
}

// ---------------- kernels ----------------

__global__ void fill_init_k() {
    int t = threadIdx.x;
    g_bin_fill[t] = t * BIN_CAP;
}

// One-pass counting-sort scatter into bump-allocated bin regions.
// Rank counters replicated by lane parity to halve smem-atomic bank conflicts.
__global__ void __launch_bounds__(256)
scatter_k(const int* __restrict__ u, const int* __restrict__ v,
          const int* __restrict__ widx, int E) {
    __shared__ int  cnt[2][N_WEIGHTS];
    __shared__ int  lstart[N_WEIGHTS];
    __shared__ int  gbase[N_WEIGHTS];
    __shared__ int  wsum[8];
    __shared__ int2 sval[SC_CHUNK];
    __shared__ unsigned char sbin[SC_CHUNK];

    const int tid  = threadIdx.x;
    const int lane = tid & 31;
    const int wrp  = tid >> 5;
    const int rep  = lane & 1;
    const int blk0 = blockIdx.x * SC_CHUNK;
    if (blk0 >= E) return;
    const int n = min(SC_CHUNK, E - blk0);

    cnt[0][tid] = 0;
    cnt[1][tid] = 0;
    __syncthreads();

    const int e0 = blk0 + tid * SC_ITER;
    const bool act = (e0 < E);

    int eu[SC_ITER], ev[SC_ITER], ew[SC_ITER], er[SC_ITER];
    if (act) {
        const int4* u4 = (const int4*)(u + e0);
        const int4* v4 = (const int4*)(v + e0);
        const int4* w4 = (const int4*)(widx + e0);
        int4 ua = u4[0], ub = u4[1];
        int4 va = v4[0], vb = v4[1];
        int4 wa = w4[0], wb = w4[1];
        eu[0]=ua.x; eu[1]=ua.y; eu[2]=ua.z; eu[3]=ua.w;
        eu[4]=ub.x; eu[5]=ub.y; eu[6]=ub.z; eu[7]=ub.w;
        ev[0]=va.x; ev[1]=va.y; ev[2]=va.z; ev[3]=va.w;
        ev[4]=vb.x; ev[5]=vb.y; ev[6]=vb.z; ev[7]=vb.w;
        ew[0]=wa.x; ew[1]=wa.y; ew[2]=wa.z; ew[3]=wa.w;
        ew[4]=wb.x; ew[5]=wb.y; ew[6]=wb.z; ew[7]=wb.w;
#pragma unroll
        for (int i = 0; i < SC_ITER; i++)
            er[i] = atomicAdd(&cnt[rep][ew[i]], 1);
    }
    __syncthreads();

    // total count per bin + shuffle-based exclusive block scan
    {
        const int c0 = cnt[0][tid];
        const int c  = c0 + cnt[1][tid];
        int s = c;
#pragma unroll
        for (int off = 1; off < 32; off <<= 1) {
            int t = __shfl_up_sync(0xffffffffu, s, off);
            if (lane >= off) s += t;
        }
        if (lane == 31) wsum[wrp] = s;
        __syncthreads();
        if (wrp == 0 && lane < 8) {
            int t = wsum[lane];
#pragma unroll
            for (int off = 1; off < 8; off <<= 1) {
                int q = __shfl_up_sync(0xffu, t, off);
                if (lane >= off) t += q;
            }
            wsum[lane] = t;
        }
        __syncthreads();
        int incl = s + (wrp ? wsum[wrp - 1] : 0);
        lstart[tid] = incl - c;
        gbase[tid]  = c ? atomicAdd(&g_bin_fill[tid], c) : 0;
    }
    __syncthreads();

    if (act) {
#pragma unroll
        for (int i = 0; i < SC_ITER; i++) {
            int b = ew[i];
            int slot = lstart[b] + er[i] + (rep ? cnt[0][b] : 0);
            sval[slot] = make_int2(eu[i], ev[i]);
            sbin[slot] = (unsigned char)b;
        }
    }
    __syncthreads();

    for (int s = tid; s < n; s += 256) {
        int b = sbin[s];
        g_suv[gbase[b] + (s - lstart[b])] = sval[s];
    }
}

// Warp-autonomous edge kernel; uv prefetched 2 iters ahead, x 1 iter ahead.
__global__ void __launch_bounds__(256)
edge_mm_k(const float* __restrict__ x, const float* __restrict__ W,
          float* __restrict__ out) {
    const int w  = blockIdx.x;
    const int bs = w * BIN_CAP;
    const int be = g_bin_fill[w];      // post-scatter: bs + bin_count

    const int tid   = threadIdx.x;
    const int lane  = tid & 31;
    const int wid   = tid >> 5;
    const int qrt   = lane & 3;
    const int el    = lane >> 2;
    const int obase = qrt * 4;

    const float* Wb = W + (size_t)w * (D * D);
    unsigned long long wp0[D], wp1[D];
#pragma unroll
    for (int k = 0; k < D; k++) {
        wp0[k] = pack2(Wb[(obase + 0) * D + k], Wb[(obase + 1) * D + k]);
        wp1[k] = pack2(Wb[(obase + 2) * D + k], Wb[(obase + 3) * D + k]);
    }

    __shared__ float4 xs[8][16 * 5];

    const float4* x4 = (const float4*)x;
    const int gw   = blockIdx.y * 8 + wid;
    const int step = gridDim.y * 8 * 16;

    int e0 = bs + gw * 16;
    if (e0 >= be) return;

    // pipeline state: uv for iters i and i+1, x for iter i
    int2 uv0A = (e0 + el     < be) ? g_suv[e0 + el]     : make_int2(0, 0);
    int2 uv0B = (e0 + 8 + el < be) ? g_suv[e0 + 8 + el] : make_int2(0, 0);
    int2 uv1A = (e0 + step + el     < be) ? g_suv[e0 + step + el]     : make_int2(0, 0);
    int2 uv1B = (e0 + step + 8 + el < be) ? g_suv[e0 + step + 8 + el] : make_int2(0, 0);
    float4 xqA = x4[(size_t)uv0A.x * 4 + qrt];
    float4 xqB = x4[(size_t)uv0B.x * 4 + qrt];

    for (; e0 < be; e0 += step) {
        const bool pA = (e0 + el     < be);
        const bool pB = (e0 + 8 + el < be);

        // prefetch uv for iter i+2
        const int e2 = e0 + 2 * step;
        int2 uv2A = (e2 + el     < be) ? g_suv[e2 + el]     : make_int2(0, 0);
        int2 uv2B = (e2 + 8 + el < be) ? g_suv[e2 + 8 + el] : make_int2(0, 0);

        // prefetch x for iter i+1 (uv1 already resident)
        float4 xnA = x4[(size_t)uv1A.x * 4 + qrt];
        float4 xnB = x4[(size_t)uv1B.x * 4 + qrt];

        // stage current x
        xs[wid][el * 5 + qrt]       = xqA;
        xs[wid][(8 + el) * 5 + qrt] = xqB;
        __syncwarp();

        unsigned long long a0A = 0ull, a1A = 0ull, a0B = 0ull, a1B = 0ull;
#pragma unroll
        for (int q = 0; q < 4; q++) {
            float4 xA = xs[wid][el * 5 + q];
            float4 xB = xs[wid][(8 + el) * 5 + q];
            unsigned long long bA0 = pack2(xA.x, xA.x), bB0 = pack2(xB.x, xB.x);
            unsigned long long bA1 = pack2(xA.y, xA.y), bB1 = pack2(xB.y, xB.y);
            unsigned long long bA2 = pack2(xA.z, xA.z), bB2 = pack2(xB.z, xB.z);
            unsigned long long bA3 = pack2(xA.w, xA.w), bB3 = pack2(xB.w, xB.w);
            fma2(a0A, wp0[q * 4 + 0], bA0);  fma2(a1A, wp1[q * 4 + 0], bA0);
            fma2(a0B, wp0[q * 4 + 0], bB0);  fma2(a1B, wp1[q * 4 + 0], bB0);
            fma2(a0A, wp0[q * 4 + 1], bA1);  fma2(a1A, wp1[q * 4 + 1], bA1);
            fma2(a0B, wp0[q * 4 + 1], bB1);  fma2(a1B, wp1[q * 4 + 1], bB1);
            fma2(a0A, wp0[q * 4 + 2], bA2);  fma2(a1A, wp1[q * 4 + 2], bA2);
            fma2(a0B, wp0[q * 4 + 2], bB2);  fma2(a1B, wp1[q * 4 + 2], bB2);
            fma2(a0A, wp0[q * 4 + 3], bA3);  fma2(a1A, wp1[q * 4 + 3], bA3);
            fma2(a0B, wp0[q * 4 + 3], bB3);  fma2(a1B, wp1[q * 4 + 3], bB3);
        }

        if (pA) {
            float r0, r1, r2, r3;
            unpack2(a0A, r0, r1);
            unpack2(a1A, r2, r3);
            red_add_v4(out + (size_t)uv0A.y * D + obase, r0, r1, r2, r3);
        }
        if (pB) {
            float r0, r1, r2, r3;
            unpack2(a0B, r0, r1);
            unpack2(a1B, r2, r3);
            red_add_v4(out + (size_t)uv0B.y * D + obase, r0, r1, r2, r3);
        }
        __syncwarp();

        // rotate pipeline
        uv0A = uv1A;  uv0B = uv1B;
        uv1A = uv2A;  uv1B = uv2B;
        xqA  = xnA;   xqB  = xnB;
    }
}

__global__ void __launch_bounds__(256)
relu_k(float* __restrict__ out, int n4) {
    int i = blockIdx.x * blockDim.x + threadIdx.x;
    if (i < n4) {
        float4* o4 = (float4*)out;
        float4 v = o4[i];
        v.x = fmaxf(v.x, 0.f);
        v.y = fmaxf(v.y, 0.f);
        v.z = fmaxf(v.z, 0.f);
        v.w = fmaxf(v.w, 0.f);
        o4[i] = v;
    }
}

// ---------------- launcher ----------------
extern "C" void kernel_launch(void* const* d_in, const int* in_sizes, int n_in,
                              void* d_out, int out_size) {
    const float* x    = (const float*)d_in[0];
    const float* W    = (const float*)d_in[1];
    const int*   u    = (const int*)d_in[2];
    const int*   v    = (const int*)d_in[3];
    const int*   widx = (const int*)d_in[4];
    float* out = (float*)d_out;

    const int E = in_sizes[2];

    cudaMemsetAsync(d_out, 0, (size_t)out_size * sizeof(float), 0);

    fill_init_k<<<1, 256>>>();
    scatter_k<<<(E + SC_CHUNK - 1) / SC_CHUNK, 256>>>(u, v, widx, E);
    edge_mm_k<<<dim3(N_WEIGHTS, MM_GRID_Y), 256>>>(x, W, out);
    int n4 = out_size / 4;
    relu_k<<<(n4 + 255) / 256, 256>>>(out, n4);
}